// round 16
// baseline (speedup 1.0000x reference)
#include <cuda_runtime.h>
#include <cuda_fp16.h>
#include <mma.h>
#include <stdlib.h>
#include <stdint.h>

using namespace nvcuda;

#define HID   1024
#define NHEAD 16
#define DHEAD 64
#define BATCH 4
#define SEQ   2048
#define MTOT  (BATCH*SEQ)

// Pure-libc ctor only (CUDA calls in ctors silently kill launches — R4-R6).
__attribute__((constructor))
static void hx_env() { setenv("CUDA_MODULE_LOADING", "EAGER", 1); }

// Scratch: 75.4 MB total (passed R12-R15).
#define PART_STRIDE ((size_t)BATCH*NHEAD*SEQ*DHEAD)
__device__ __align__(16) __half g_qkv[(size_t)3*PART_STRIDE]; // part0=Q->attn out
__device__ __align__(16) __half g_wa[(size_t)HID*3*HID];
__device__ __align__(16) __half g_wp[(size_t)HID*HID];
__device__ __align__(16) __half g_x16[(size_t)MTOT*HID];

// ---- asm helpers ------------------------------------------------------------
#define CP_ASYNC16(dst_u32, src_ptr) \
    asm volatile("cp.async.cg.shared.global [%0], [%1], 16;" \
                 :: "r"(dst_u32), "l"(src_ptr))
#define CP_COMMIT()  asm volatile("cp.async.commit_group;")
#define CP_WAIT1()   asm volatile("cp.async.wait_group 1;")
#define CP_WAIT0()   asm volatile("cp.async.wait_group 0;")

#define LDMX4(r0,r1,r2,r3,addr) \
    asm volatile("ldmatrix.sync.aligned.m8n8.x4.shared.b16 {%0,%1,%2,%3}, [%4];" \
                 : "=r"(r0),"=r"(r1),"=r"(r2),"=r"(r3) : "r"(addr))
#define LDMX4T(r0,r1,r2,r3,addr) \
    asm volatile("ldmatrix.sync.aligned.m8n8.x4.trans.shared.b16 {%0,%1,%2,%3}, [%4];" \
                 : "=r"(r0),"=r"(r1),"=r"(r2),"=r"(r3) : "r"(addr))

#define MMA16816(d, a, b0, b1) \
    asm volatile("mma.sync.aligned.m16n8k16.row.col.f32.f16.f16.f32 " \
                 "{%0,%1,%2,%3}, {%4,%5,%6,%7}, {%8,%9}, {%0,%1,%2,%3};" \
                 : "+f"((d)[0]), "+f"((d)[1]), "+f"((d)[2]), "+f"((d)[3]) \
                 : "r"((a)[0]), "r"((a)[1]), "r"((a)[2]), "r"((a)[3]), \
                   "r"(b0), "r"(b1))

__device__ __forceinline__ uint32_t h2pack(float a, float b) {
    const __half2 h = __floats2half2_rn(a, b);
    return *reinterpret_cast<const uint32_t*>(&h);
}

// ---------------------------------------------------------------------------
// Kernel 0: fp32 -> fp16 conversion of W_attn, W_proj, and x.
// ---------------------------------------------------------------------------
__global__ __launch_bounds__(256)
void conv_kernel(const float* __restrict__ Wa, const float* __restrict__ Wp,
                 const float* __restrict__ x)
{
    const int NA4 = HID*3*HID/4;
    const int NP4 = HID*HID/4;
    const int NX4 = MTOT*HID/4;
    const int i = blockIdx.x * 256 + threadIdx.x;
    const float4* src;
    __half2* dst;
    int j;
    if (i < NA4)                { src = (const float4*)Wa; dst = (__half2*)g_wa;  j = i; }
    else if (i < NA4 + NP4)     { src = (const float4*)Wp; dst = (__half2*)g_wp;  j = i - NA4; }
    else if (i < NA4+NP4+NX4)   { src = (const float4*)x;  dst = (__half2*)g_x16; j = i - NA4 - NP4; }
    else return;
    const float4 v = src[j];
    dst[2*(size_t)j]     = __floats2half2_rn(v.x, v.y);
    dst[2*(size_t)j + 1] = __floats2half2_rn(v.z, v.w);
}

// ---------------------------------------------------------------------------
// GEMM skeleton v2: 128x128 tile, k-chunk 64, cp.async double buffer in
// DYNAMIC smem (71.7 KB). Halves sync count vs k-chunk 32 and doubles the
// MMA train per sync window.
// Stage: Ah[128][72] f16 (18.4KB) + Bh[64][136] f16 (17.4KB).
// ---------------------------------------------------------------------------
#define ACH   72
#define BCH   136
#define STG_A (128*ACH)            // 9216 halves
#define STG_B (64*BCH)             // 8704 halves
#define STAGE (STG_A + STG_B)      // 17920 halves = 35840 B
#define GEMM_SMEM (2*STAGE*2)      // 71680 B

__global__ __launch_bounds__(256)
void qkv_kernel(const float* __restrict__ bias)
{
    extern __shared__ __align__(16) __half sm[];

    const int tid = threadIdx.x, w = tid >> 5;
    const int m0 = blockIdx.y * 128, n0 = blockIdx.x * 128;
    const int wm = (w >> 1) * 32, wn = (w & 1) * 64;
    const uint32_t smb = (uint32_t)__cvta_generic_to_shared(sm);

    wmma::fragment<wmma::accumulator, 16, 16, 16, float> c[2][4];
#pragma unroll
    for (int mi = 0; mi < 2; mi++)
#pragma unroll
        for (int ni = 0; ni < 4; ni++) wmma::fill_fragment(c[mi][ni], 0.f);

    auto prefetch = [&](int kc, int stg) {
        const int k0 = kc * 64;
        const uint32_t sa = smb + stg * STAGE * 2;
        const uint32_t sb = sa + STG_A * 2;
#pragma unroll
        for (int t = 0; t < 4; t++) {              // A 128x64: 1024 chunks16
            const int idx = tid + t * 256;
            const int r = idx >> 3, c8 = idx & 7;
            CP_ASYNC16(sa + (r*ACH + c8*8)*2,
                       &g_x16[(size_t)(m0 + r)*HID + k0 + c8*8]);
        }
#pragma unroll
        for (int t = 0; t < 4; t++) {              // B 64x128: 1024 chunks16
            const int idx = tid + t * 256;
            const int r = idx >> 4, c8 = idx & 15;
            CP_ASYNC16(sb + (r*BCH + c8*8)*2,
                       &g_wa[(size_t)(k0 + r)*3072 + n0 + c8*8]);
        }
        CP_COMMIT();
    };

    prefetch(0, 0);
    const int NCH = HID / 64;                      // 16
    for (int kc = 0; kc < NCH; kc++) {
        if (kc + 1 < NCH) { prefetch(kc + 1, (kc + 1) & 1); CP_WAIT1(); }
        else              { CP_WAIT0(); }
        __syncthreads();

        const __half* Ah = sm + (kc & 1) * STAGE;
        const __half* Bh = Ah + STG_A;
#pragma unroll
        for (int kk = 0; kk < 4; kk++) {
            wmma::fragment<wmma::matrix_a, 16, 16, 16, __half, wmma::row_major> a[2];
#pragma unroll
            for (int mi = 0; mi < 2; mi++)
                wmma::load_matrix_sync(a[mi], Ah + (wm + 16*mi)*ACH + 16*kk, ACH);
#pragma unroll
            for (int ni = 0; ni < 4; ni++) {
                wmma::fragment<wmma::matrix_b, 16, 16, 16, __half, wmma::row_major> b;
                wmma::load_matrix_sync(b, Bh + 16*kk*BCH + wn + 16*ni, BCH);
                wmma::mma_sync(c[0][ni], a[0], b, c[0][ni]);
                wmma::mma_sync(c[1][ni], a[1], b, c[1][ni]);
            }
        }
        __syncthreads();
    }

    float* Cst = reinterpret_cast<float*>(sm);
#pragma unroll
    for (int hf = 0; hf < 2; hf++) {
        if ((w & 1) == hf) {
#pragma unroll
            for (int mi = 0; mi < 2; mi++)
#pragma unroll
                for (int ni = 0; ni < 4; ni++)
                    wmma::store_matrix_sync(&Cst[(wm + 16*mi)*64 + 16*ni],
                                            c[mi][ni], 64, wmma::mem_row_major);
        }
        __syncthreads();
        for (int i = tid; i < 8192; i += 256) {
            const int r = i >> 6, cl = i & 63;
            const int cg = n0 + hf*64 + cl;
            const float v = Cst[r*64 + cl] + bias[cg];
            const int part = cg >> 10;
            const int hc = cg & 1023, hh = hc >> 6, dd = hc & 63;
            const int rg = m0 + r, bb = rg >> 11, s = rg & 2047;
            g_qkv[(size_t)part*PART_STRIDE +
                  (((size_t)(bb*NHEAD + hh))*SEQ + s)*DHEAD + dd] = __float2half(v);
        }
        __syncthreads();
    }
}

__global__ __launch_bounds__(256)
void proj_kernel(const float* __restrict__ bias, float* __restrict__ out)
{
    extern __shared__ __align__(16) __half sm[];

    const int tid = threadIdx.x, w = tid >> 5;
    const int m0 = blockIdx.y * 128, n0 = blockIdx.x * 128;
    const int wm = (w >> 1) * 32, wn = (w & 1) * 64;
    const uint32_t smb = (uint32_t)__cvta_generic_to_shared(sm);

    wmma::fragment<wmma::accumulator, 16, 16, 16, float> c[2][4];
#pragma unroll
    for (int mi = 0; mi < 2; mi++)
#pragma unroll
        for (int ni = 0; ni < 4; ni++) wmma::fill_fragment(c[mi][ni], 0.f);

    auto prefetch = [&](int kc, int stg) {
        const int k0 = kc * 64;
        const int hh = kc;                          // chunk == one head
        const uint32_t sa = smb + stg * STAGE * 2;
        const uint32_t sb = sa + STG_A * 2;
#pragma unroll
        for (int t = 0; t < 4; t++) {
            const int idx = tid + t * 256;
            const int r = idx >> 3, c8 = idx & 7;
            const int rg = m0 + r, bb = rg >> 11, s = rg & 2047;
            CP_ASYNC16(sa + (r*ACH + c8*8)*2,
                       &g_qkv[(((size_t)(bb*NHEAD + hh))*SEQ + s)*DHEAD + c8*8]);
        }
#pragma unroll
        for (int t = 0; t < 4; t++) {
            const int idx = tid + t * 256;
            const int r = idx >> 4, c8 = idx & 15;
            CP_ASYNC16(sb + (r*BCH + c8*8)*2,
                       &g_wp[(size_t)(k0 + r)*HID + n0 + c8*8]);
        }
        CP_COMMIT();
    };

    prefetch(0, 0);
    const int NCH = HID / 64;
    for (int kc = 0; kc < NCH; kc++) {
        if (kc + 1 < NCH) { prefetch(kc + 1, (kc + 1) & 1); CP_WAIT1(); }
        else              { CP_WAIT0(); }
        __syncthreads();

        const __half* Ah = sm + (kc & 1) * STAGE;
        const __half* Bh = Ah + STG_A;
#pragma unroll
        for (int kk = 0; kk < 4; kk++) {
            wmma::fragment<wmma::matrix_a, 16, 16, 16, __half, wmma::row_major> a[2];
#pragma unroll
            for (int mi = 0; mi < 2; mi++)
                wmma::load_matrix_sync(a[mi], Ah + (wm + 16*mi)*ACH + 16*kk, ACH);
#pragma unroll
            for (int ni = 0; ni < 4; ni++) {
                wmma::fragment<wmma::matrix_b, 16, 16, 16, __half, wmma::row_major> b;
                wmma::load_matrix_sync(b, Bh + 16*kk*BCH + wn + 16*ni, BCH);
                wmma::mma_sync(c[0][ni], a[0], b, c[0][ni]);
                wmma::mma_sync(c[1][ni], a[1], b, c[1][ni]);
            }
        }
        __syncthreads();
    }

    float* Cst = reinterpret_cast<float*>(sm);
#pragma unroll
    for (int hf = 0; hf < 2; hf++) {
        if ((w & 1) == hf) {
#pragma unroll
            for (int mi = 0; mi < 2; mi++)
#pragma unroll
                for (int ni = 0; ni < 4; ni++)
                    wmma::store_matrix_sync(&Cst[(wm + 16*mi)*64 + 16*ni],
                                            c[mi][ni], 64, wmma::mem_row_major);
        }
        __syncthreads();
        for (int i = tid; i < 8192; i += 256) {
            const int r = i >> 6, cl = i & 63;
            const int cg = n0 + hf*64 + cl;
            out[(size_t)(m0 + r)*HID + cg] = Cst[r*64 + cl] + bias[cg];
        }
        __syncthreads();
    }
}

// ---------------------------------------------------------------------------
// Kernel 2: flash v4 (proven R15) + longest-first scheduling: block with the
// largest qb (most K-tiles) launches first, removing the wave tail.
// ---------------------------------------------------------------------------
__global__ __launch_bounds__(128, 4)
void flash_kernel()
{
    __shared__ __align__(16) __half Kt[64*72];
    __shared__ __align__(16) __half Vt[64*72];
    __shared__ __align__(16) __half Qs[4][16*72];

    const int qb = (gridDim.x - 1) - blockIdx.x;   // longest-first
    const int hh = blockIdx.y, b = blockIdx.z;
    const int q0 = qb * 64;
    const int tid = threadIdx.x;
    const int w = tid >> 5, lane = tid & 31;

    const __half* qbase = g_qkv + ((size_t)(b * NHEAD + hh)) * SEQ * DHEAD;
    const __half* kbase = qbase + PART_STRIDE;
    const __half* vbase = qbase + 2 * PART_STRIDE;
    const uint32_t kt_s = (uint32_t)__cvta_generic_to_shared(Kt);
    const uint32_t vt_s = (uint32_t)__cvta_generic_to_shared(Vt);
    const uint32_t qs_s = (uint32_t)__cvta_generic_to_shared(Qs[w]);

    const int arow = (lane & 7) + ((lane >> 3) & 1) * 8;
    const int acol = ((lane >> 4) & 1) * 8;
    const int vrow = (lane & 7) + ((lane >> 4) & 1) * 8;
    const int vcol = ((lane >> 3) & 1) * 8;

    for (int t = lane; t < 128; t += 32) {
        const int r = t >> 3, c8 = t & 7;
        *reinterpret_cast<float4*>(&Qs[w][r * 72 + c8 * 8]) =
            *reinterpret_cast<const float4*>(
                &qbase[(size_t)(q0 + 16*w + r) * 64 + c8 * 8]);
    }
    __syncwarp();
    uint32_t qa[4][4];
#pragma unroll
    for (int kk = 0; kk < 4; kk++) {
        const uint32_t addr = qs_s + (arow * 72 + 16*kk + acol) * 2;
        LDMX4(qa[kk][0], qa[kk][1], qa[kk][2], qa[kk][3], addr);
    }

    float O[8][4];
#pragma unroll
    for (int ni = 0; ni < 8; ni++)
#pragma unroll
        for (int cc = 0; cc < 4; cc++) O[ni][cc] = 0.f;
    float m0 = -1e30f, m1 = -1e30f, l0 = 0.f, l1 = 0.f;

    const int rg0 = q0 + 16*w + (lane >> 2);
    const int rg1 = rg0 + 8;

    const int nkt = qb + 1;
    for (int kt = 0; kt < nkt; kt++) {
        const int k0 = kt * 64;
        for (int t = tid; t < 1024; t += 128) {
            if (t < 512) {
                const int r = t >> 3, c8 = t & 7;
                CP_ASYNC16(kt_s + (r * 72 + c8 * 8) * 2,
                           &kbase[(size_t)(k0 + r) * 64 + c8 * 8]);
            } else {
                const int u = t - 512, r = u >> 3, c8 = u & 7;
                CP_ASYNC16(vt_s + (r * 72 + c8 * 8) * 2,
                           &vbase[(size_t)(k0 + r) * 64 + c8 * 8]);
            }
        }
        CP_COMMIT();
        CP_WAIT0();
        __syncthreads();

        float S[8][4];
#pragma unroll
        for (int ni = 0; ni < 8; ni++)
#pragma unroll
            for (int cc = 0; cc < 4; cc++) S[ni][cc] = 0.f;
#pragma unroll
        for (int kk = 0; kk < 4; kk++) {
#pragma unroll
            for (int nj = 0; nj < 4; nj++) {
                uint32_t r0, r1, r2, r3;
                const uint32_t addr =
                    kt_s + ((16*nj + arow) * 72 + 16*kk + acol) * 2;
                LDMX4(r0, r1, r2, r3, addr);
                MMA16816(S[2*nj],     qa[kk], r0, r2);
                MMA16816(S[2*nj + 1], qa[kk], r1, r3);
            }
        }

        float mx0 = -1e30f, mx1 = -1e30f;
#pragma unroll
        for (int ni = 0; ni < 8; ni++) {
            const int cb = k0 + 8*ni + (lane & 3) * 2;
            S[ni][0] = (cb     <= rg0) ? S[ni][0] * 0.125f : -1e30f;
            S[ni][1] = (cb + 1 <= rg0) ? S[ni][1] * 0.125f : -1e30f;
            S[ni][2] = (cb     <= rg1) ? S[ni][2] * 0.125f : -1e30f;
            S[ni][3] = (cb + 1 <= rg1) ? S[ni][3] * 0.125f : -1e30f;
            mx0 = fmaxf(mx0, fmaxf(S[ni][0], S[ni][1]));
            mx1 = fmaxf(mx1, fmaxf(S[ni][2], S[ni][3]));
        }
        mx0 = fmaxf(mx0, __shfl_xor_sync(0xffffffffu, mx0, 1));
        mx0 = fmaxf(mx0, __shfl_xor_sync(0xffffffffu, mx0, 2));
        mx1 = fmaxf(mx1, __shfl_xor_sync(0xffffffffu, mx1, 1));
        mx1 = fmaxf(mx1, __shfl_xor_sync(0xffffffffu, mx1, 2));

        const float mn0 = fmaxf(m0, mx0), mn1 = fmaxf(m1, mx1);
        const float a0 = __expf(m0 - mn0), a1 = __expf(m1 - mn1);
        m0 = mn0; m1 = mn1;

        float s0 = 0.f, s1 = 0.f;
#pragma unroll
        for (int ni = 0; ni < 8; ni++) {
            S[ni][0] = __expf(S[ni][0] - mn0);
            S[ni][1] = __expf(S[ni][1] - mn0);
            S[ni][2] = __expf(S[ni][2] - mn1);
            S[ni][3] = __expf(S[ni][3] - mn1);
            s0 += S[ni][0] + S[ni][1];
            s1 += S[ni][2] + S[ni][3];
        }
        s0 += __shfl_xor_sync(0xffffffffu, s0, 1);
        s0 += __shfl_xor_sync(0xffffffffu, s0, 2);
        s1 += __shfl_xor_sync(0xffffffffu, s1, 1);
        s1 += __shfl_xor_sync(0xffffffffu, s1, 2);
        l0 = l0 * a0 + s0;
        l1 = l1 * a1 + s1;

#pragma unroll
        for (int ni = 0; ni < 8; ni++) {
            O[ni][0] *= a0; O[ni][1] *= a0;
            O[ni][2] *= a1; O[ni][3] *= a1;
        }

        uint32_t pa[4][4];
#pragma unroll
        for (int kk = 0; kk < 4; kk++) {
            pa[kk][0] = h2pack(S[2*kk][0],     S[2*kk][1]);
            pa[kk][1] = h2pack(S[2*kk][2],     S[2*kk][3]);
            pa[kk][2] = h2pack(S[2*kk + 1][0], S[2*kk + 1][1]);
            pa[kk][3] = h2pack(S[2*kk + 1][2], S[2*kk + 1][3]);
        }

#pragma unroll
        for (int kk = 0; kk < 4; kk++) {
#pragma unroll
            for (int nj = 0; nj < 4; nj++) {
                uint32_t r0, r1, r2, r3;
                const uint32_t addr =
                    vt_s + ((16*kk + vrow) * 72 + 16*nj + vcol) * 2;
                LDMX4T(r0, r1, r2, r3, addr);
                MMA16816(O[2*nj],     pa[kk], r0, r2);
                MMA16816(O[2*nj + 1], pa[kk], r1, r3);
            }
        }

        __syncthreads();
    }

    {
        const float i0 = 1.f / l0, i1 = 1.f / l1;
        __half* ob0 = g_qkv + ((size_t)(b * NHEAD + hh)) * SEQ * DHEAD
                      + (size_t)rg0 * 64;
        __half* ob1 = g_qkv + ((size_t)(b * NHEAD + hh)) * SEQ * DHEAD
                      + (size_t)rg1 * 64;
#pragma unroll
        for (int ni = 0; ni < 8; ni++) {
            const int col = 8*ni + (lane & 3) * 2;
            *reinterpret_cast<uint32_t*>(ob0 + col) =
                h2pack(O[ni][0] * i0, O[ni][1] * i0);
            *reinterpret_cast<uint32_t*>(ob1 + col) =
                h2pack(O[ni][2] * i1, O[ni][3] * i1);
        }
    }
}

// ---------------------------------------------------------------------------
// kernel_launch: kernel launches + cudaFuncSetAttribute (capture-safe: not a
// stream-ordered API; R4's "0 nodes" was the cudaFree ctor, proven by R5
// failing identically without any attribute call). Idempotent, deterministic,
// allocation-free.
// ---------------------------------------------------------------------------
extern "C" void kernel_launch(void* const* d_in, const int* in_sizes, int n_in,
                              void* d_out, int out_size)
{
    const float* x      = (const float*)d_in[0];
    const float* W_attn = (const float*)d_in[1];
    const float* b_attn = (const float*)d_in[2];
    const float* W_proj = (const float*)d_in[3];
    const float* b_proj = (const float*)d_in[4];
    float* out = (float*)d_out;

    cudaFuncSetAttribute(qkv_kernel,
                         cudaFuncAttributeMaxDynamicSharedMemorySize, GEMM_SMEM);
    cudaFuncSetAttribute(proj_kernel,
                         cudaFuncAttributeMaxDynamicSharedMemorySize, GEMM_SMEM);

    conv_kernel<<<12288, 256>>>(W_attn, W_proj, x);
    {
        dim3 grid(3 * HID / 128, MTOT / 128);   // (24, 64)
        qkv_kernel<<<grid, 256, GEMM_SMEM>>>(b_attn);
    }
    {
        dim3 grid(SEQ / 64, NHEAD, BATCH);      // (32, 16, 4)
        flash_kernel<<<grid, 128>>>();
    }
    {
        dim3 grid(HID / 128, MTOT / 128);       // (8, 64)
        proj_kernel<<<grid, 256, GEMM_SMEM>>>(b_proj, out);
    }
}